// round 4
// baseline (speedup 1.0000x reference)
#include <cuda_runtime.h>
#include <cuda_bf16.h>
#include <math.h>

// ---------------- problem constants ----------------
#define TT  32      // timesteps
#define BB  64      // batch
#define HH  512     // hidden
#define EE  512     // embed
#define MLL 64      // encoder length
#define VV  32000   // vocab
#define NL  2       // lstm layers

typedef unsigned long long ull;

// ---------------- persistent device state (no allocations allowed) ----------------
__device__ float g_h[NL][BB][HH];        // hidden state
__device__ float g_c[NL][BB][HH];        // cell state
__device__ float g_X[TT][BB][HH];        // top-layer h per step (rows of final vocab GEMM)
__device__ float g_cat2[BB][2 * EE];     // [emb | ctx] per step
__device__ float g_rp[4][BB][EE];        // rnn_in K-split partials
__device__ float g_x0[BB][EE];           // layer-0 input (relu'd rnn_in)
__device__ float g_gp[4][BB][4 * HH];    // gates K-split partials

__device__ __forceinline__ float sigf(float x) { return 1.0f / (1.0f + expf(-x)); }

// ---------------- init: copy h0/c0 into state ----------------
__global__ void k_init(const float* __restrict__ h0, const float* __restrict__ c0) {
    int i = blockIdx.x * 256 + threadIdx.x;
    if (i < NL * BB * HH) {
        ((float*)g_h)[i] = h0[i];
        ((float*)g_c)[i] = c0[i];
    }
}

// ---------------- attention: one block per batch element ----------------
// emb lookup -> scores over ML=64 (K=1024) -> softmax -> ctx -> writes g_cat2
__global__ void __launch_bounds__(256) k_attn(
    const int* __restrict__ tok,
    const float* __restrict__ emb,       // [V][E]
    const float* __restrict__ attn_W,    // [ML][E+H]
    const float* __restrict__ enc)       // [ML][B][H]
{
    int b = blockIdx.x;
    int tid = threadIdx.x;
    __shared__ float av[2 * EE];
    __shared__ float sc[MLL];

    int t = tok[b];
    const float* er = emb + (size_t)t * EE;
    for (int i = tid; i < EE; i += 256) {
        float v = er[i];
        av[i] = v;
        g_cat2[b][i] = v;                // left half of cat2 = embedding row
    }
    const float* hr = &g_h[NL - 1][b][0];
    for (int i = tid; i < HH; i += 256) av[EE + i] = hr[i];
    __syncthreads();

    int w = tid >> 5, lane = tid & 31;
    for (int m = w; m < MLL; m += 8) {
        const float* wr = attn_W + (size_t)m * (EE + HH);
        float s = 0.f;
        #pragma unroll 8
        for (int k = lane; k < EE + HH; k += 32) s = fmaf(av[k], wr[k], s);
        #pragma unroll
        for (int o = 16; o; o >>= 1) s += __shfl_xor_sync(0xffffffffu, s, o);
        if (lane == 0) sc[m] = s;
    }
    __syncthreads();

    if (tid < 32) {  // softmax over 64 values, one warp, 2 per lane
        float a0 = sc[tid], a1 = sc[tid + 32];
        float m = fmaxf(a0, a1);
        #pragma unroll
        for (int o = 16; o; o >>= 1) m = fmaxf(m, __shfl_xor_sync(0xffffffffu, m, o));
        float e0 = expf(a0 - m), e1 = expf(a1 - m);
        float s = e0 + e1;
        #pragma unroll
        for (int o = 16; o; o >>= 1) s += __shfl_xor_sync(0xffffffffu, s, o);
        float inv = 1.0f / s;
        sc[tid] = e0 * inv;
        sc[tid + 32] = e1 * inv;
    }
    __syncthreads();

    for (int h = tid; h < HH; h += 256) {     // ctx[h] = sum_m a[m]*enc[m][b][h]
        float acc = 0.f;
        #pragma unroll 8
        for (int m = 0; m < MLL; m++)
            acc = fmaf(sc[m], enc[((size_t)m * BB + b) * HH + h], acc);
        g_cat2[b][EE + h] = acc;
    }
}

// ---------------- generic tiled GEMM: C[M,N] (+=partials) = A[M,K] @ W[N,K]^T ----------------
// 64x64 block tile, BK=16, 4x4 microtile with packed fma.rn.f32x2 accumulators.
// A source selected device-side (aSel), C dest selected device-side (cSel).
// gridDim.z = K-split count; each z-slice writes its own partial plane.
__global__ void __launch_bounds__(256) k_gemm(
    int aSel,                         // 0: g_cat2(K=1024) 1: [g_x0|g_h0] 2: [g_h0|g_h1] 3: g_X(K=512)
    const float* __restrict__ W1, int ldw1,
    const float* __restrict__ W2, int ldw2,
    int K1, int Ktot,
    const float* __restrict__ bias,
    float* __restrict__ Cout, int cSel)   // cSel 0: g_rp  1: g_gp  2: Cout (ldc=VV)
{
    __shared__ float As[16][68];
    __shared__ float Ws[16][68];

    const float *A1, *A2 = nullptr;
    int lda1, lda2 = 0;
    switch (aSel) {
        case 0: A1 = &g_cat2[0][0]; lda1 = 2 * EE; break;
        case 1: A1 = &g_x0[0][0];   lda1 = EE; A2 = &g_h[0][0][0]; lda2 = HH; break;
        case 2: A1 = &g_h[0][0][0]; lda1 = HH; A2 = &g_h[1][0][0]; lda2 = HH; break;
        default:A1 = &g_X[0][0][0]; lda1 = HH; break;
    }
    float* C; long long ldc, pstr;
    switch (cSel) {
        case 0:  C = &g_rp[0][0][0]; ldc = EE;     pstr = (long long)BB * EE;     break;
        case 1:  C = &g_gp[0][0][0]; ldc = 4 * HH; pstr = (long long)BB * 4 * HH; break;
        default: C = Cout;           ldc = VV;     pstr = 0;                      break;
    }

    int tid  = threadIdx.x;
    int n0   = blockIdx.x * 64;
    int m0   = blockIdx.y * 64;
    int Ksp  = Ktot / gridDim.z;
    int kz0  = blockIdx.z * Ksp;
    C += (long long)blockIdx.z * pstr;

    int bq = (tid & 15) * 4;       // M offset of 4-row microtile
    int jq = (tid >> 4) * 4;       // N offset of 4-col microtile
    int arow = tid >> 2;           // 0..63 : tile row loaded by this thread
    int akk  = (tid & 3) * 4;      // 0,4,8,12 : k offset within BK chunk

    ull acc[4][2];
    #pragma unroll
    for (int i = 0; i < 4; i++) { acc[i][0] = 0ull; acc[i][1] = 0ull; }

    for (int k0 = kz0; k0 < kz0 + Ksp; k0 += 16) {
        int kg = k0 + akk;
        float4 av, wv;
        if (kg < K1) av = *(const float4*)&A1[(size_t)(m0 + arow) * lda1 + kg];
        else         av = *(const float4*)&A2[(size_t)(m0 + arow) * lda2 + (kg - K1)];
        if (kg < K1) wv = *(const float4*)&W1[(size_t)(n0 + arow) * ldw1 + kg];
        else         wv = *(const float4*)&W2[(size_t)(n0 + arow) * ldw2 + (kg - K1)];
        As[akk + 0][arow] = av.x; As[akk + 1][arow] = av.y;
        As[akk + 2][arow] = av.z; As[akk + 3][arow] = av.w;
        Ws[akk + 0][arow] = wv.x; Ws[akk + 1][arow] = wv.y;
        Ws[akk + 2][arow] = wv.z; Ws[akk + 3][arow] = wv.w;
        __syncthreads();

        #pragma unroll
        for (int kk = 0; kk < 16; kk++) {
            float4 a4 = *(const float4*)&As[kk][bq];
            ull w01 = *(const ull*)&Ws[kk][jq];
            ull w23 = *(const ull*)&Ws[kk][jq + 2];
            float a_[4] = {a4.x, a4.y, a4.z, a4.w};
            #pragma unroll
            for (int i = 0; i < 4; i++) {
                ull aa;
                unsigned u = __float_as_uint(a_[i]);
                asm("mov.b64 %0, {%1, %2};" : "=l"(aa) : "r"(u), "r"(u));
                asm("fma.rn.f32x2 %0, %1, %2, %0;" : "+l"(acc[i][0]) : "l"(aa), "l"(w01));
                asm("fma.rn.f32x2 %0, %1, %2, %0;" : "+l"(acc[i][1]) : "l"(aa), "l"(w23));
            }
        }
        __syncthreads();
    }

    #pragma unroll
    for (int i = 0; i < 4; i++) {
        unsigned lo0, hi0, lo1, hi1;
        asm("mov.b64 {%0, %1}, %2;" : "=r"(lo0), "=r"(hi0) : "l"(acc[i][0]));
        asm("mov.b64 {%0, %1}, %2;" : "=r"(lo1), "=r"(hi1) : "l"(acc[i][1]));
        float4 v = { __uint_as_float(lo0), __uint_as_float(hi0),
                     __uint_as_float(lo1), __uint_as_float(hi1) };
        int col = n0 + jq;
        if (bias) {
            v.x += bias[col]; v.y += bias[col + 1];
            v.z += bias[col + 2]; v.w += bias[col + 3];
        }
        *(float4*)&C[(long long)(m0 + bq + i) * ldc + col] = v;
    }
}

// ---------------- sum rnn_in K-partials + relu -> g_x0 ----------------
__global__ void k_comb() {
    int i = blockIdx.x * 256 + threadIdx.x;   // BB*EE = 32768
    const float* p = (const float*)g_rp;
    float s = p[i] + p[BB * EE + i] + p[2 * BB * EE + i] + p[3 * BB * EE + i];
    ((float*)g_x0)[i] = fmaxf(s, 0.0f);
}

// ---------------- LSTM cell: sum gate partials + bias, update h/c ----------------
__global__ void k_cell(const float* __restrict__ bi, const float* __restrict__ bh,
                       int l, int t) {
    int idx = blockIdx.x * 256 + threadIdx.x;  // BB*HH = 32768
    int b = idx >> 9, h = idx & 511;
    float gi = 0.f, gf = 0.f, gg = 0.f, go = 0.f;
    #pragma unroll
    for (int s = 0; s < 4; s++) {
        gi += g_gp[s][b][h];
        gf += g_gp[s][b][512 + h];
        gg += g_gp[s][b][1024 + h];
        go += g_gp[s][b][1536 + h];
    }
    const float* bip = bi + (size_t)l * 4 * HH;
    const float* bhp = bh + (size_t)l * 4 * HH;
    gi += bip[h]        + bhp[h];
    gf += bip[512 + h]  + bhp[512 + h];
    gg += bip[1024 + h] + bhp[1024 + h];
    go += bip[1536 + h] + bhp[1536 + h];

    float c  = g_c[l][b][h];
    float cn = sigf(gf) * c + sigf(gi) * tanhf(gg);
    float hn = sigf(go) * tanhf(cn);
    g_c[l][b][h] = cn;
    g_h[l][b][h] = hn;
    if (l == NL - 1) g_X[t][b][h] = hn;
}

// ---------------- final state copy (h_fin, c_fin) ----------------
__global__ void k_fin(float* __restrict__ out) {
    int i = blockIdx.x * 256 + threadIdx.x;
    int n = NL * BB * HH;
    if (i < n)           out[i] = ((const float*)g_h)[i];
    else if (i < 2 * n)  out[i] = ((const float*)g_c)[i - n];
}

// ---------------- launch ----------------
extern "C" void kernel_launch(void* const* d_in, const int* in_sizes, int n_in,
                              void* d_out, int out_size) {
    // input order: current_input, h0, c0, encoder_output, gtruth, [length],
    //              emb, attn_W, attn_out_W, lstm_Wi, lstm_Wh, lstm_bi, lstm_bh, gen_W, gen_b
    int o = (n_in >= 15) ? 1 : 0;   // optional scalar 'length' at index 5
    const int*   cur        = (const int*)  d_in[0];
    const float* h0         = (const float*)d_in[1];
    const float* c0         = (const float*)d_in[2];
    const float* enc        = (const float*)d_in[3];
    const int*   gtr        = (const int*)  d_in[4];
    const float* emb        = (const float*)d_in[5 + o];
    const float* attn_W     = (const float*)d_in[6 + o];
    const float* attn_out_W = (const float*)d_in[7 + o];
    const float* Wi         = (const float*)d_in[8 + o];
    const float* Wh         = (const float*)d_in[9 + o];
    const float* bi         = (const float*)d_in[10 + o];
    const float* bh         = (const float*)d_in[11 + o];
    const float* gen_W      = (const float*)d_in[12 + o];
    const float* gen_b      = (const float*)d_in[13 + o];
    float* out = (float*)d_out;

    k_init<<<(NL * BB * HH + 255) / 256, 256>>>(h0, c0);

    for (int t = 0; t < TT; t++) {
        const int* tok = (t == 0) ? cur : (gtr + (size_t)(t - 1) * BB);
        k_attn<<<BB, 256>>>(tok, emb, attn_W, enc);

        // rnn_in partials: [64,512] = cat2[64,1024] @ attn_out_W[512,1024]^T, K-split 4
        {
            dim3 g(EE / 64, 1, 4);
            k_gemm<<<g, 256>>>(0, attn_out_W, 2 * EE, nullptr, 0,
                               2 * EE, 2 * EE, nullptr, nullptr, 0);
        }
        k_comb<<<(BB * EE) / 256, 256>>>();

        for (int l = 0; l < NL; l++) {
            // gates partials: [64,2048] = [x|h_l][64,1024] @ [Wi_l|Wh_l][2048,1024]^T, K-split 4
            dim3 g(4 * HH / 64, 1, 4);
            k_gemm<<<g, 256>>>((l == 0) ? 1 : 2,
                               Wi + (size_t)l * 4 * HH * EE, EE,
                               Wh + (size_t)l * 4 * HH * HH, HH,
                               EE, EE + HH, nullptr, nullptr, 1);
            k_cell<<<(BB * HH) / 256, 256>>>(bi, bh, l, t);
        }
    }

    // batched vocab GEMM: [T*B, V] = g_X[2048,512] @ gen_W[32000,512]^T + gen_b
    {
        dim3 g(VV / 64, (TT * BB) / 64, 1);
        k_gemm<<<g, 256>>>(3, gen_W, HH, nullptr, 0,
                           HH, HH, gen_b, out, 2);
    }

    size_t sn = (size_t)TT * BB * VV;
    if ((size_t)out_size >= sn + (size_t)2 * NL * BB * HH)
        k_fin<<<(2 * NL * BB * HH + 255) / 256, 256>>>(out + sn);
}

// round 7
// speedup vs baseline: 1.6313x; 1.6313x over previous
#include <cuda_runtime.h>
#include <cuda_bf16.h>
#include <math.h>
#include <stdint.h>

// ---------------- problem constants ----------------
#define TT  32      // timesteps
#define BB  64      // batch
#define HH  512     // hidden
#define EE  512     // embed
#define MLL 64      // encoder length
#define VV  32000   // vocab
#define NL  2       // lstm layers
#define KS  8       // K-split factor for recurrence GEMMs
#define KP  1536    // split-bf16 GEMM K (3 x 512)

typedef unsigned long long ull;

// ---------------- persistent device state (no allocations allowed) ----------------
__device__ float g_h[NL][BB][HH];
__device__ float g_c[NL][BB][HH];
__device__ float g_X[TT][BB][HH];         // top-layer h per step
__device__ float g_cat2[BB][2 * EE];
__device__ float g_rp[KS][BB][EE];
__device__ float g_x0[BB][EE];
__device__ float g_gp[KS][BB][4 * HH];
// bf16-split operands for the tensor-core vocab GEMM
__device__ __nv_bfloat16 g_Ap[(size_t)TT * BB * KP];   // [2048][1536] = [Ah|Ah|Al]
__device__ __nv_bfloat16 g_Wp[(size_t)VV * KP];        // [32000][1536] = [Wh|Wl|Wh]

__device__ __forceinline__ float sigf(float x) { return 1.0f / (1.0f + expf(-x)); }

__device__ __forceinline__ uint32_t smem_u32(const void* p) {
    uint32_t a;
    asm("{ .reg .u64 t; cvta.to.shared.u64 t, %1; cvt.u32.u64 %0, t; }" : "=r"(a) : "l"(p));
    return a;
}

// ---------------- init ----------------
__global__ void k_init(const float* __restrict__ h0, const float* __restrict__ c0) {
    int i = blockIdx.x * 256 + threadIdx.x;
    if (i < NL * BB * HH) {
        ((float*)g_h)[i] = h0[i];
        ((float*)g_c)[i] = c0[i];
    }
}

// ---------------- attention ----------------
__global__ void __launch_bounds__(256) k_attn(
    const int* __restrict__ tok,
    const float* __restrict__ emb,
    const float* __restrict__ attn_W,
    const float* __restrict__ enc)
{
    int b = blockIdx.x;
    int tid = threadIdx.x;
    __shared__ float av[2 * EE];
    __shared__ float sc[MLL];

    int t = tok[b];
    const float* er = emb + (size_t)t * EE;
    for (int i = tid; i < EE; i += 256) {
        float v = er[i];
        av[i] = v;
        g_cat2[b][i] = v;
    }
    const float* hr = &g_h[NL - 1][b][0];
    for (int i = tid; i < HH; i += 256) av[EE + i] = hr[i];
    __syncthreads();

    int w = tid >> 5, lane = tid & 31;
    for (int m = w; m < MLL; m += 8) {
        const float* wr = attn_W + (size_t)m * (EE + HH);
        float s = 0.f;
        #pragma unroll 8
        for (int k = lane; k < EE + HH; k += 32) s = fmaf(av[k], wr[k], s);
        #pragma unroll
        for (int o = 16; o; o >>= 1) s += __shfl_xor_sync(0xffffffffu, s, o);
        if (lane == 0) sc[m] = s;
    }
    __syncthreads();

    if (tid < 32) {
        float a0 = sc[tid], a1 = sc[tid + 32];
        float m = fmaxf(a0, a1);
        #pragma unroll
        for (int o = 16; o; o >>= 1) m = fmaxf(m, __shfl_xor_sync(0xffffffffu, m, o));
        float e0 = expf(a0 - m), e1 = expf(a1 - m);
        float s = e0 + e1;
        #pragma unroll
        for (int o = 16; o; o >>= 1) s += __shfl_xor_sync(0xffffffffu, s, o);
        float inv = 1.0f / s;
        sc[tid] = e0 * inv;
        sc[tid + 32] = e1 * inv;
    }
    __syncthreads();

    for (int h = tid; h < HH; h += 256) {
        float acc = 0.f;
        #pragma unroll 8
        for (int m = 0; m < MLL; m++)
            acc = fmaf(sc[m], enc[((size_t)m * BB + b) * HH + h], acc);
        g_cat2[b][EE + h] = acc;
    }
}

// ---------------- generic tiled GEMM for the recurrence (fp32 f32x2) ----------------
__global__ void __launch_bounds__(256) k_gemm(
    int aSel,
    const float* __restrict__ W1, int ldw1,
    const float* __restrict__ W2, int ldw2,
    int K1, int Ktot,
    int cSel)   // cSel 0: g_rp  1: g_gp
{
    __shared__ float As[16][68];
    __shared__ float Ws[16][68];

    const float *A1, *A2 = nullptr;
    int lda1, lda2 = 0;
    switch (aSel) {
        case 0: A1 = &g_cat2[0][0]; lda1 = 2 * EE; break;
        case 1: A1 = &g_x0[0][0];   lda1 = EE; A2 = &g_h[0][0][0]; lda2 = HH; break;
        default:A1 = &g_h[0][0][0]; lda1 = HH; A2 = &g_h[1][0][0]; lda2 = HH; break;
    }
    float* C; long long ldc, pstr;
    if (cSel == 0) { C = &g_rp[0][0][0]; ldc = EE;     pstr = (long long)BB * EE; }
    else           { C = &g_gp[0][0][0]; ldc = 4 * HH; pstr = (long long)BB * 4 * HH; }

    int tid  = threadIdx.x;
    int n0   = blockIdx.x * 64;
    int m0   = blockIdx.y * 64;
    int Ksp  = Ktot / gridDim.z;
    int kz0  = blockIdx.z * Ksp;
    C += (long long)blockIdx.z * pstr;

    int bq = (tid & 15) * 4;
    int jq = (tid >> 4) * 4;
    int arow = tid >> 2;
    int akk  = (tid & 3) * 4;

    ull acc[4][2];
    #pragma unroll
    for (int i = 0; i < 4; i++) { acc[i][0] = 0ull; acc[i][1] = 0ull; }

    for (int k0 = kz0; k0 < kz0 + Ksp; k0 += 16) {
        int kg = k0 + akk;
        float4 av, wv;
        if (kg < K1) av = *(const float4*)&A1[(size_t)(m0 + arow) * lda1 + kg];
        else         av = *(const float4*)&A2[(size_t)(m0 + arow) * lda2 + (kg - K1)];
        if (kg < K1) wv = *(const float4*)&W1[(size_t)(n0 + arow) * ldw1 + kg];
        else         wv = *(const float4*)&W2[(size_t)(n0 + arow) * ldw2 + (kg - K1)];
        As[akk + 0][arow] = av.x; As[akk + 1][arow] = av.y;
        As[akk + 2][arow] = av.z; As[akk + 3][arow] = av.w;
        Ws[akk + 0][arow] = wv.x; Ws[akk + 1][arow] = wv.y;
        Ws[akk + 2][arow] = wv.z; Ws[akk + 3][arow] = wv.w;
        __syncthreads();

        #pragma unroll
        for (int kk = 0; kk < 16; kk++) {
            float4 a4 = *(const float4*)&As[kk][bq];
            ull w01 = *(const ull*)&Ws[kk][jq];
            ull w23 = *(const ull*)&Ws[kk][jq + 2];
            float a_[4] = {a4.x, a4.y, a4.z, a4.w};
            #pragma unroll
            for (int i = 0; i < 4; i++) {
                ull aa;
                unsigned u = __float_as_uint(a_[i]);
                asm("mov.b64 %0, {%1, %2};" : "=l"(aa) : "r"(u), "r"(u));
                asm("fma.rn.f32x2 %0, %1, %2, %0;" : "+l"(acc[i][0]) : "l"(aa), "l"(w01));
                asm("fma.rn.f32x2 %0, %1, %2, %0;" : "+l"(acc[i][1]) : "l"(aa), "l"(w23));
            }
        }
        __syncthreads();
    }

    #pragma unroll
    for (int i = 0; i < 4; i++) {
        unsigned lo0, hi0, lo1, hi1;
        asm("mov.b64 {%0, %1}, %2;" : "=r"(lo0), "=r"(hi0) : "l"(acc[i][0]));
        asm("mov.b64 {%0, %1}, %2;" : "=r"(lo1), "=r"(hi1) : "l"(acc[i][1]));
        float4 v = { __uint_as_float(lo0), __uint_as_float(hi0),
                     __uint_as_float(lo1), __uint_as_float(hi1) };
        *(float4*)&C[(long long)(m0 + bq + i) * ldc + (n0 + jq)] = v;
    }
}

// ---------------- sum rnn_in partials + relu ----------------
__global__ void k_comb() {
    int i = blockIdx.x * 256 + threadIdx.x;
    const float* p = (const float*)g_rp;
    float s = 0.f;
    #pragma unroll
    for (int q = 0; q < KS; q++) s += p[(size_t)q * BB * EE + i];
    ((float*)g_x0)[i] = fmaxf(s, 0.0f);
}

// ---------------- LSTM cell ----------------
__global__ void k_cell(const float* __restrict__ bi, const float* __restrict__ bh,
                       int l, int t) {
    int idx = blockIdx.x * 256 + threadIdx.x;
    int b = idx >> 9, h = idx & 511;
    float gi = 0.f, gf = 0.f, gg = 0.f, go = 0.f;
    #pragma unroll
    for (int s = 0; s < KS; s++) {
        gi += g_gp[s][b][h];
        gf += g_gp[s][b][512 + h];
        gg += g_gp[s][b][1024 + h];
        go += g_gp[s][b][1536 + h];
    }
    const float* bip = bi + (size_t)l * 4 * HH;
    const float* bhp = bh + (size_t)l * 4 * HH;
    gi += bip[h]        + bhp[h];
    gf += bip[512 + h]  + bhp[512 + h];
    gg += bip[1024 + h] + bhp[1024 + h];
    go += bip[1536 + h] + bhp[1536 + h];

    float c  = g_c[l][b][h];
    float cn = sigf(gf) * c + sigf(gi) * tanhf(gg);
    float hn = sigf(go) * tanhf(cn);
    g_c[l][b][h] = cn;
    g_h[l][b][h] = hn;
    if (l == NL - 1) g_X[t][b][h] = hn;
}

// ---------------- bf16-split conversions ----------------
// W' row layout over K'=1536: [Wh(512) | Wl(512) | Wh(512)]
__global__ void __launch_bounds__(256) k_cvtW(const float* __restrict__ W) {
    size_t t = (size_t)blockIdx.x * 256 + threadIdx.x;   // VV*512/4 threads
    size_t row = t >> 7;
    int kq = (int)(t & 127) * 4;
    float4 v = *(const float4*)(W + row * 512 + kq);
    __nv_bfloat16 h0 = __float2bfloat16_rn(v.x), h1 = __float2bfloat16_rn(v.y);
    __nv_bfloat16 h2 = __float2bfloat16_rn(v.z), h3 = __float2bfloat16_rn(v.w);
    __nv_bfloat16 l0 = __float2bfloat16_rn(v.x - __bfloat162float(h0));
    __nv_bfloat16 l1 = __float2bfloat16_rn(v.y - __bfloat162float(h1));
    __nv_bfloat16 l2 = __float2bfloat16_rn(v.z - __bfloat162float(h2));
    __nv_bfloat16 l3 = __float2bfloat16_rn(v.w - __bfloat162float(h3));
    __nv_bfloat16* d = &g_Wp[row * KP + kq];
    *(__nv_bfloat162*)(d)        = __nv_bfloat162(h0, h1);
    *(__nv_bfloat162*)(d + 2)    = __nv_bfloat162(h2, h3);
    *(__nv_bfloat162*)(d + 512)  = __nv_bfloat162(l0, l1);
    *(__nv_bfloat162*)(d + 514)  = __nv_bfloat162(l2, l3);
    *(__nv_bfloat162*)(d + 1024) = __nv_bfloat162(h0, h1);
    *(__nv_bfloat162*)(d + 1026) = __nv_bfloat162(h2, h3);
}

// A' row layout over K'=1536: [Ah(512) | Ah(512) | Al(512)]
__global__ void __launch_bounds__(256) k_cvtA() {
    size_t t = (size_t)blockIdx.x * 256 + threadIdx.x;   // 2048*512/4 threads
    size_t row = t >> 7;
    int kq = (int)(t & 127) * 4;
    float4 v = *(const float4*)((const float*)g_X + row * 512 + kq);
    __nv_bfloat16 h0 = __float2bfloat16_rn(v.x), h1 = __float2bfloat16_rn(v.y);
    __nv_bfloat16 h2 = __float2bfloat16_rn(v.z), h3 = __float2bfloat16_rn(v.w);
    __nv_bfloat16 l0 = __float2bfloat16_rn(v.x - __bfloat162float(h0));
    __nv_bfloat16 l1 = __float2bfloat16_rn(v.y - __bfloat162float(h1));
    __nv_bfloat16 l2 = __float2bfloat16_rn(v.z - __bfloat162float(h2));
    __nv_bfloat16 l3 = __float2bfloat16_rn(v.w - __bfloat162float(h3));
    __nv_bfloat16* d = &g_Ap[row * KP + kq];
    *(__nv_bfloat162*)(d)        = __nv_bfloat162(h0, h1);
    *(__nv_bfloat162*)(d + 2)    = __nv_bfloat162(h2, h3);
    *(__nv_bfloat162*)(d + 512)  = __nv_bfloat162(h0, h1);
    *(__nv_bfloat162*)(d + 514)  = __nv_bfloat162(h2, h3);
    *(__nv_bfloat162*)(d + 1024) = __nv_bfloat162(l0, l1);
    *(__nv_bfloat162*)(d + 1026) = __nv_bfloat162(l2, l3);
}

// ---------------- vocab GEMM via warp-level mma.sync (bf16 -> fp32) ----------------
// C[2048, 32000] = A'[2048,1536] @ W'[32000,1536]^T + gen_b
// CTA: 128x128 tile, 8 warps (4 in M x 2 in N), warp tile 32x64, BK=32,
// double-buffered smem, ONE __syncthreads per chunk.
#define VBK 32
#define LDA 40     // padded smem row length (bf16 units) -> 80B row stride

__global__ void __launch_bounds__(256) k_vocab(const float* __restrict__ gen_b,
                                               float* __restrict__ out)
{
    __shared__ __nv_bfloat16 sA[2][128 * LDA];
    __shared__ __nv_bfloat16 sB[2][128 * LDA];

    int tid = threadIdx.x;
    int wid = tid >> 5, lane = tid & 31;
    int n0 = blockIdx.x * 128;
    int m0 = blockIdx.y * 128;
    int wm = (wid & 3) * 32;     // warp M offset within tile
    int wn = (wid >> 2) * 64;    // warp N offset within tile

    float acc[2][8][4];
    #pragma unroll
    for (int a = 0; a < 2; a++)
        #pragma unroll
        for (int b = 0; b < 8; b++)
            #pragma unroll
            for (int q = 0; q < 4; q++) acc[a][b][q] = 0.f;

    // tile loader: 128 rows x 32 bf16 = 512 float4; 256 threads x 2 rows each.
    // thread covers rows (tid>>2) and (tid>>2)+64, k-segment (tid&3)*8.
    int lrow = tid >> 2;               // 0..63
    int lseg = (tid & 3) * 8;          // 0,8,16,24
    const __nv_bfloat16* Ag0 = g_Ap + (size_t)(m0 + lrow)      * KP + lseg;
    const __nv_bfloat16* Ag1 = g_Ap + (size_t)(m0 + lrow + 64) * KP + lseg;
    const __nv_bfloat16* Bg0 = g_Wp + (size_t)(n0 + lrow)      * KP + lseg;
    const __nv_bfloat16* Bg1 = g_Wp + (size_t)(n0 + lrow + 64) * KP + lseg;
    int sr0 = lrow * LDA + lseg;
    int sr1 = (lrow + 64) * LDA + lseg;

    // preload chunk 0
    float4 ra0 = *(const float4*)Ag0;
    float4 ra1 = *(const float4*)Ag1;
    float4 rb0 = *(const float4*)Bg0;
    float4 rb1 = *(const float4*)Bg1;

    const int NCH = KP / VBK;   // 48
    for (int c = 0; c < NCH; c++) {
        int cur = c & 1;
        // store current chunk regs -> buf[cur] (last read of buf[cur] was chunk c-2,
        // separated by the sync in iteration c-1)
        *(float4*)&sA[cur][sr0] = ra0;
        *(float4*)&sA[cur][sr1] = ra1;
        *(float4*)&sB[cur][sr0] = rb0;
        *(float4*)&sB[cur][sr1] = rb1;
        if (c + 1 < NCH) {               // issue next-chunk loads (latency hidden by compute)
            ra0 = *(const float4*)(Ag0 + (c + 1) * VBK);
            ra1 = *(const float4*)(Ag1 + (c + 1) * VBK);
            rb0 = *(const float4*)(Bg0 + (c + 1) * VBK);
            rb1 = *(const float4*)(Bg1 + (c + 1) * VBK);
        }
        __syncthreads();

        #pragma unroll
        for (int ks = 0; ks < 2; ks++) {
            int kc = ks * 16;
            uint32_t afr[2][4];
            #pragma unroll
            for (int am = 0; am < 2; am++) {
                int row = wm + am * 16 + (lane & 15);
                int col = kc + (lane >> 4) * 8;
                uint32_t addr = smem_u32(&sA[cur][row * LDA + col]);
                asm volatile("ldmatrix.sync.aligned.m8n8.x4.shared.b16 {%0,%1,%2,%3}, [%4];"
                    : "=r"(afr[am][0]), "=r"(afr[am][1]), "=r"(afr[am][2]), "=r"(afr[am][3])
                    : "r"(addr));
            }
            uint32_t bfr[4][4];
            #pragma unroll
            for (int bn = 0; bn < 4; bn++) {
                int sub = lane >> 3;
                int row = wn + bn * 16 + (sub >> 1) * 8 + (lane & 7);
                int col = kc + (sub & 1) * 8;
                uint32_t addr = smem_u32(&sB[cur][row * LDA + col]);
                asm volatile("ldmatrix.sync.aligned.m8n8.x4.shared.b16 {%0,%1,%2,%3}, [%4];"
                    : "=r"(bfr[bn][0]), "=r"(bfr[bn][1]), "=r"(bfr[bn][2]), "=r"(bfr[bn][3])
                    : "r"(addr));
            }
            #pragma unroll
            for (int am = 0; am < 2; am++) {
                #pragma unroll
                for (int bn = 0; bn < 8; bn++) {
                    uint32_t b0 = bfr[bn >> 1][(bn & 1) * 2];
                    uint32_t b1 = bfr[bn >> 1][(bn & 1) * 2 + 1];
                    asm volatile(
                        "mma.sync.aligned.m16n8k16.row.col.f32.bf16.bf16.f32 "
                        "{%0,%1,%2,%3}, {%4,%5,%6,%7}, {%8,%9}, {%0,%1,%2,%3};"
                        : "+f"(acc[am][bn][0]), "+f"(acc[am][bn][1]),
                          "+f"(acc[am][bn][2]), "+f"(acc[am][bn][3])
                        : "r"(afr[am][0]), "r"(afr[am][1]), "r"(afr[am][2]), "r"(afr[am][3]),
                          "r"(b0), "r"(b1));
                }
            }
        }
        // no second sync: next iteration writes the OTHER buffer; writes to this
        // buffer happen two iterations later, after the next sync.
    }

    // epilogue
    int group = lane >> 2, tq = (lane & 3) * 2;
    #pragma unroll
    for (int am = 0; am < 2; am++) {
        #pragma unroll
        for (int bn = 0; bn < 8; bn++) {
            int r0 = m0 + wm + am * 16 + group;
            int cx = n0 + wn + bn * 8 + tq;
            float b0 = gen_b[cx], b1 = gen_b[cx + 1];
            float2 v0 = { acc[am][bn][0] + b0, acc[am][bn][1] + b1 };
            float2 v1 = { acc[am][bn][2] + b0, acc[am][bn][3] + b1 };
            *(float2*)&out[(size_t)r0 * VV + cx]       = v0;
            *(float2*)&out[(size_t)(r0 + 8) * VV + cx] = v1;
        }
    }
}

// ---------------- final state copy ----------------
__global__ void k_fin(float* __restrict__ out) {
    int i = blockIdx.x * 256 + threadIdx.x;
    int n = NL * BB * HH;
    if (i < n)           out[i] = ((const float*)g_h)[i];
    else if (i < 2 * n)  out[i] = ((const float*)g_c)[i - n];
}

// ---------------- launch ----------------
extern "C" void kernel_launch(void* const* d_in, const int* in_sizes, int n_in,
                              void* d_out, int out_size) {
    int o = (n_in >= 15) ? 1 : 0;   // optional scalar 'length'
    const int*   cur        = (const int*)  d_in[0];
    const float* h0         = (const float*)d_in[1];
    const float* c0         = (const float*)d_in[2];
    const float* enc        = (const float*)d_in[3];
    const int*   gtr        = (const int*)  d_in[4];
    const float* emb        = (const float*)d_in[5 + o];
    const float* attn_W     = (const float*)d_in[6 + o];
    const float* attn_out_W = (const float*)d_in[7 + o];
    const float* Wi         = (const float*)d_in[8 + o];
    const float* Wh         = (const float*)d_in[9 + o];
    const float* bi         = (const float*)d_in[10 + o];
    const float* bh         = (const float*)d_in[11 + o];
    const float* gen_W      = (const float*)d_in[12 + o];
    const float* gen_b      = (const float*)d_in[13 + o];
    float* out = (float*)d_out;

    k_init<<<(NL * BB * HH + 255) / 256, 256>>>(h0, c0);
    k_cvtW<<<(VV * 512 / 4 + 255) / 256, 256>>>(gen_W);   // W split (overlaps recurrence)

    for (int t = 0; t < TT; t++) {
        const int* tok = (t == 0) ? cur : (gtr + (size_t)(t - 1) * BB);
        k_attn<<<BB, 256>>>(tok, emb, attn_W, enc);

        {   // rnn_in partials: K=1024 split KS ways
            dim3 g(EE / 64, 1, KS);
            k_gemm<<<g, 256>>>(0, attn_out_W, 2 * EE, nullptr, 0, 2 * EE, 2 * EE, 0);
        }
        k_comb<<<(BB * EE) / 256, 256>>>();

        for (int l = 0; l < NL; l++) {
            dim3 g(4 * HH / 64, 1, KS);
            k_gemm<<<g, 256>>>((l == 0) ? 1 : 2,
                               Wi + (size_t)l * 4 * HH * EE, EE,
                               Wh + (size_t)l * 4 * HH * HH, HH,
                               EE, EE + HH, 1);
            k_cell<<<(BB * HH) / 256, 256>>>(bi, bh, l, t);
        }
    }

    // split A and run the tensor-core vocab GEMM
    k_cvtA<<<(TT * BB * 512 / 4 + 255) / 256, 256>>>();
    {
        dim3 g(VV / 128, (TT * BB) / 128);
        k_vocab<<<g, 256>>>(gen_b, out);
    }

    size_t sn = (size_t)TT * BB * VV;
    if ((size_t)out_size >= sn + (size_t)2 * NL * BB * HH)
        k_fin<<<(2 * NL * BB * HH + 255) / 256, 256>>>(out + sn);
}

// round 8
// speedup vs baseline: 1.9160x; 1.1745x over previous
#include <cuda_runtime.h>
#include <cuda_bf16.h>
#include <math.h>
#include <stdint.h>

// ---------------- problem constants ----------------
#define TT  32      // timesteps
#define BB  64      // batch
#define HH  512     // hidden
#define EE  512     // embed
#define MLL 64      // encoder length
#define VV  32000   // vocab
#define NL  2       // lstm layers
#define KS  8       // K-split factor for recurrence GEMMs
#define KP  1536    // vocab split-bf16 K (3 x 512)
#define KR  3072    // recurrence split-bf16 K (3 x 1024)

typedef unsigned long long ull;

// ---------------- persistent device state (no allocations allowed) ----------------
__device__ float g_h[NL][BB][HH];
__device__ float g_c[NL][BB][HH];
__device__ float g_rp[KS][BB][EE];        // rnn_in K-split partials
__device__ float g_gp[KS][BB][4 * HH];    // gate K-split partials
// split-bf16 activations (A' = [Ah | Ah | Al])
__device__ __nv_bfloat16 g_A1[BB][KR];        // cat2 split  [emb|ctx]
__device__ __nv_bfloat16 g_GA[2][BB][KR];     // gate input split per layer: [x | h]
// split-bf16 weights (W' = [Wh | Wl | Wh]) -- converted once per launch
__device__ __nv_bfloat16 g_AOW[EE][KR];       // attn_out_W split
__device__ __nv_bfloat16 g_GW[NL][4 * HH][KR];// [Wi_l | Wh_l] split
// vocab GEMM operands
__device__ __nv_bfloat16 g_Ap[(size_t)TT * BB * KP];   // [2048][1536] = [Ah|Ah|Al]
__device__ __nv_bfloat16 g_Wp[(size_t)VV * KP];        // [32000][1536] = [Wh|Wl|Wh]

__device__ __forceinline__ float sigf(float x) { return 1.0f / (1.0f + expf(-x)); }

__device__ __forceinline__ uint32_t smem_u32(const void* p) {
    uint32_t a;
    asm("{ .reg .u64 t; cvta.to.shared.u64 t, %1; cvt.u32.u64 %0, t; }" : "=r"(a) : "l"(p));
    return a;
}

// split one float into (hi, lo) bf16
__device__ __forceinline__ void bsplit(float v, __nv_bfloat16& hi, __nv_bfloat16& lo) {
    hi = __float2bfloat16_rn(v);
    lo = __float2bfloat16_rn(v - __bfloat162float(hi));
}

// ---------------- init: state copy + h split into gate-A h-slots ----------------
__global__ void k_init(const float* __restrict__ h0, const float* __restrict__ c0) {
    int i = blockIdx.x * 256 + threadIdx.x;
    if (i < NL * BB * HH) {
        ((float*)g_h)[i] = h0[i];
        ((float*)g_c)[i] = c0[i];
        int l = i >> 15, r = i & 32767;
        int b = r >> 9, h = r & 511;
        __nv_bfloat16 hi, lo;
        bsplit(h0[i], hi, lo);
        g_GA[l][b][512 + h]  = hi;
        g_GA[l][b][1536 + h] = hi;
        g_GA[l][b][2560 + h] = lo;
    }
}

// ---------------- attention (writes cat2 directly in split form) ----------------
__global__ void __launch_bounds__(256) k_attn(
    const int* __restrict__ tok,
    const float* __restrict__ emb,
    const float* __restrict__ attn_W,
    const float* __restrict__ enc)
{
    int b = blockIdx.x;
    int tid = threadIdx.x;
    __shared__ float av[2 * EE];
    __shared__ float sc[MLL];

    int t = tok[b];
    const float* er = emb + (size_t)t * EE;
    for (int i = tid; i < EE; i += 256) {
        float v = er[i];
        av[i] = v;
        __nv_bfloat16 hi, lo;
        bsplit(v, hi, lo);
        g_A1[b][i] = hi; g_A1[b][1024 + i] = hi; g_A1[b][2048 + i] = lo;
    }
    const float* hr = &g_h[NL - 1][b][0];
    for (int i = tid; i < HH; i += 256) av[EE + i] = hr[i];
    __syncthreads();

    int w = tid >> 5, lane = tid & 31;
    for (int m = w; m < MLL; m += 8) {
        const float* wr = attn_W + (size_t)m * (EE + HH);
        float s = 0.f;
        #pragma unroll 8
        for (int k = lane; k < EE + HH; k += 32) s = fmaf(av[k], wr[k], s);
        #pragma unroll
        for (int o = 16; o; o >>= 1) s += __shfl_xor_sync(0xffffffffu, s, o);
        if (lane == 0) sc[m] = s;
    }
    __syncthreads();

    if (tid < 32) {
        float a0 = sc[tid], a1 = sc[tid + 32];
        float m = fmaxf(a0, a1);
        #pragma unroll
        for (int o = 16; o; o >>= 1) m = fmaxf(m, __shfl_xor_sync(0xffffffffu, m, o));
        float e0 = expf(a0 - m), e1 = expf(a1 - m);
        float s = e0 + e1;
        #pragma unroll
        for (int o = 16; o; o >>= 1) s += __shfl_xor_sync(0xffffffffu, s, o);
        float inv = 1.0f / s;
        sc[tid] = e0 * inv;
        sc[tid + 32] = e1 * inv;
    }
    __syncthreads();

    for (int h = tid; h < HH; h += 256) {
        float acc = 0.f;
        #pragma unroll 8
        for (int m = 0; m < MLL; m++)
            acc = fmaf(sc[m], enc[((size_t)m * BB + b) * HH + h], acc);
        __nv_bfloat16 hi, lo;
        bsplit(acc, hi, lo);
        g_A1[b][512 + h] = hi; g_A1[b][1536 + h] = hi; g_A1[b][2560 + h] = lo;
    }
}

// ---------------- recurrence GEMM on tensor cores ----------------
// Cp[z][64][Ntot] = A'[64,KR] @ W'[Ntot,KR]^T  (K-split over gridDim.z)
// sel 0: rnn_in (A=g_A1, W=g_AOW, N=512, Cp=g_rp)
// sel 1: gates l0 (A=g_GA[0], W=g_GW[0], N=2048, Cp=g_gp)
// sel 2: gates l1 (A=g_GA[1], W=g_GW[1], N=2048, Cp=g_gp)
#define LDA 40

__global__ void __launch_bounds__(256) k_rgemm(int sel) {
    __shared__ __nv_bfloat16 sA[2][64 * LDA];
    __shared__ __nv_bfloat16 sB[2][128 * LDA];

    const __nv_bfloat16* A = (sel == 0) ? &g_A1[0][0]
                           : (sel == 1) ? &g_GA[0][0][0] : &g_GA[1][0][0];
    const __nv_bfloat16* W = (sel == 0) ? &g_AOW[0][0]
                           : (sel == 1) ? &g_GW[0][0][0] : &g_GW[1][0][0];
    int Ntot = (sel == 0) ? EE : 4 * HH;
    float* Cp = (sel == 0) ? &g_rp[0][0][0] : &g_gp[0][0][0];

    int tid = threadIdx.x;
    int wid = tid >> 5, lane = tid & 31;
    int n0 = blockIdx.x * 128;
    int wm = (wid & 3) * 16;     // warp M offset (M=64 -> 4 warps)
    int wn = (wid >> 2) * 64;    // warp N offset
    const int NCH = (KR / 32) / KS;     // 12 chunks per z-slice
    int c0 = blockIdx.z * NCH;

    float acc[8][4];
    #pragma unroll
    for (int b = 0; b < 8; b++)
        #pragma unroll
        for (int q = 0; q < 4; q++) acc[b][q] = 0.f;

    int lrow = tid >> 2;               // 0..63
    int lseg = (tid & 3) * 8;
    const __nv_bfloat16* Ag  = A + (size_t)lrow * KR + c0 * 32 + lseg;
    const __nv_bfloat16* Bg0 = W + (size_t)(n0 + lrow)      * KR + c0 * 32 + lseg;
    const __nv_bfloat16* Bg1 = W + (size_t)(n0 + lrow + 64) * KR + c0 * 32 + lseg;
    int srA = lrow * LDA + lseg;
    int sr1 = (lrow + 64) * LDA + lseg;

    float4 ra  = *(const float4*)Ag;
    float4 rb0 = *(const float4*)Bg0;
    float4 rb1 = *(const float4*)Bg1;

    for (int c = 0; c < NCH; c++) {
        int cur = c & 1;
        *(float4*)&sA[cur][srA] = ra;
        *(float4*)&sB[cur][srA] = rb0;
        *(float4*)&sB[cur][sr1] = rb1;
        if (c + 1 < NCH) {
            ra  = *(const float4*)(Ag  + (c + 1) * 32);
            rb0 = *(const float4*)(Bg0 + (c + 1) * 32);
            rb1 = *(const float4*)(Bg1 + (c + 1) * 32);
        }
        __syncthreads();

        #pragma unroll
        for (int ks = 0; ks < 2; ks++) {
            int kc = ks * 16;
            uint32_t afr[4];
            {
                int row = wm + (lane & 15);
                int col = kc + (lane >> 4) * 8;
                uint32_t addr = smem_u32(&sA[cur][row * LDA + col]);
                asm volatile("ldmatrix.sync.aligned.m8n8.x4.shared.b16 {%0,%1,%2,%3}, [%4];"
                    : "=r"(afr[0]), "=r"(afr[1]), "=r"(afr[2]), "=r"(afr[3]) : "r"(addr));
            }
            uint32_t bfr[4][4];
            #pragma unroll
            for (int bn = 0; bn < 4; bn++) {
                int sub = lane >> 3;
                int row = wn + bn * 16 + (sub >> 1) * 8 + (lane & 7);
                int col = kc + (sub & 1) * 8;
                uint32_t addr = smem_u32(&sB[cur][row * LDA + col]);
                asm volatile("ldmatrix.sync.aligned.m8n8.x4.shared.b16 {%0,%1,%2,%3}, [%4];"
                    : "=r"(bfr[bn][0]), "=r"(bfr[bn][1]), "=r"(bfr[bn][2]), "=r"(bfr[bn][3])
                    : "r"(addr));
            }
            #pragma unroll
            for (int bn = 0; bn < 8; bn++) {
                uint32_t b0 = bfr[bn >> 1][(bn & 1) * 2];
                uint32_t b1 = bfr[bn >> 1][(bn & 1) * 2 + 1];
                asm volatile(
                    "mma.sync.aligned.m16n8k16.row.col.f32.bf16.bf16.f32 "
                    "{%0,%1,%2,%3}, {%4,%5,%6,%7}, {%8,%9}, {%0,%1,%2,%3};"
                    : "+f"(acc[bn][0]), "+f"(acc[bn][1]), "+f"(acc[bn][2]), "+f"(acc[bn][3])
                    : "r"(afr[0]), "r"(afr[1]), "r"(afr[2]), "r"(afr[3]), "r"(b0), "r"(b1));
            }
        }
    }

    int group = lane >> 2, tq = (lane & 3) * 2;
    float* Co = Cp + (size_t)blockIdx.z * 64 * Ntot;
    #pragma unroll
    for (int bn = 0; bn < 8; bn++) {
        int r0 = wm + group;
        int cx = n0 + wn + bn * 8 + tq;
        float2 v0 = { acc[bn][0], acc[bn][1] };
        float2 v1 = { acc[bn][2], acc[bn][3] };
        *(float2*)&Co[(size_t)r0 * Ntot + cx]       = v0;
        *(float2*)&Co[(size_t)(r0 + 8) * Ntot + cx] = v1;
    }
}

// ---------------- sum rnn_in partials + relu -> split into gate-A l0 x-slot ----------------
__global__ void k_comb() {
    int i = blockIdx.x * 256 + threadIdx.x;   // BB*EE
    int b = i >> 9, col = i & 511;
    const float* p = (const float*)g_rp;
    float s = 0.f;
    #pragma unroll
    for (int q = 0; q < KS; q++) s += p[(size_t)q * BB * EE + i];
    s = fmaxf(s, 0.0f);
    __nv_bfloat16 hi, lo;
    bsplit(s, hi, lo);
    g_GA[0][b][col] = hi; g_GA[0][b][1024 + col] = hi; g_GA[0][b][2048 + col] = lo;
}

// ---------------- LSTM cell: sum partials + bias, update, write split outputs ----------------
__global__ void k_cell(const float* __restrict__ bi, const float* __restrict__ bh,
                       int l, int t) {
    int idx = blockIdx.x * 256 + threadIdx.x;  // BB*HH
    int b = idx >> 9, h = idx & 511;
    float gi = 0.f, gf = 0.f, gg = 0.f, go = 0.f;
    #pragma unroll
    for (int s = 0; s < KS; s++) {
        gi += g_gp[s][b][h];
        gf += g_gp[s][b][512 + h];
        gg += g_gp[s][b][1024 + h];
        go += g_gp[s][b][1536 + h];
    }
    const float* bip = bi + (size_t)l * 4 * HH;
    const float* bhp = bh + (size_t)l * 4 * HH;
    gi += bip[h]        + bhp[h];
    gf += bip[512 + h]  + bhp[512 + h];
    gg += bip[1024 + h] + bhp[1024 + h];
    go += bip[1536 + h] + bhp[1536 + h];

    float c  = g_c[l][b][h];
    float cn = sigf(gf) * c + sigf(gi) * tanhf(gg);
    float hn = sigf(go) * tanhf(cn);
    g_c[l][b][h] = cn;
    g_h[l][b][h] = hn;

    __nv_bfloat16 hi, lo;
    bsplit(hn, hi, lo);
    if (l == 0) {
        // x-input of layer 1 (this step)
        g_GA[1][b][h] = hi; g_GA[1][b][1024 + h] = hi; g_GA[1][b][2048 + h] = lo;
        // h-input of layer 0 (next step)
        g_GA[0][b][512 + h] = hi; g_GA[0][b][1536 + h] = hi; g_GA[0][b][2560 + h] = lo;
    } else {
        // h-input of layer 1 (next step)
        g_GA[1][b][512 + h] = hi; g_GA[1][b][1536 + h] = hi; g_GA[1][b][2560 + h] = lo;
        // vocab GEMM A' row (t*BB + b)
        __nv_bfloat16* d = &g_Ap[(size_t)(t * BB + b) * KP];
        d[h] = hi; d[512 + h] = hi; d[1024 + h] = lo;
    }
}

// ---------------- one-time weight splits ----------------
// gen_W -> g_Wp  (vocab): [Wh(512)|Wl(512)|Wh(512)]
__global__ void __launch_bounds__(256) k_cvtW(const float* __restrict__ W) {
    size_t t = (size_t)blockIdx.x * 256 + threadIdx.x;   // VV*512/4
    size_t row = t >> 7;
    int kq = (int)(t & 127) * 4;
    float4 v = *(const float4*)(W + row * 512 + kq);
    __nv_bfloat16 h0, l0, h1, l1, h2, l2, h3, l3;
    bsplit(v.x, h0, l0); bsplit(v.y, h1, l1); bsplit(v.z, h2, l2); bsplit(v.w, h3, l3);
    __nv_bfloat16* d = &g_Wp[row * KP + kq];
    *(__nv_bfloat162*)(d)        = __nv_bfloat162(h0, h1);
    *(__nv_bfloat162*)(d + 2)    = __nv_bfloat162(h2, h3);
    *(__nv_bfloat162*)(d + 512)  = __nv_bfloat162(l0, l1);
    *(__nv_bfloat162*)(d + 514)  = __nv_bfloat162(l2, l3);
    *(__nv_bfloat162*)(d + 1024) = __nv_bfloat162(h0, h1);
    *(__nv_bfloat162*)(d + 1026) = __nv_bfloat162(h2, h3);
}

// [Wi_l | Wh_l] -> g_GW[l]: row n over K=1024 -> [Wh(1024)|Wl(1024)|Wh(1024)]
__global__ void __launch_bounds__(256) k_cvtGW(const float* __restrict__ Wi,
                                               const float* __restrict__ Wh) {
    size_t t = (size_t)blockIdx.x * 256 + threadIdx.x;   // NL*2048*1024/4
    if (t >= (size_t)NL * 4 * HH * 1024 / 4) return;
    size_t e = t * 4;
    int l = (int)(e >> 21);                 // / (2048*1024)
    size_t r = e & ((1u << 21) - 1);
    int n = (int)(r >> 10);
    int k = (int)(r & 1023);
    float4 v;
    if (k < 512) v = *(const float4*)(Wi + ((size_t)l * 4 * HH + n) * 512 + k);
    else         v = *(const float4*)(Wh + ((size_t)l * 4 * HH + n) * 512 + (k - 512));
    __nv_bfloat16 h0, l0, h1, l1, h2, l2, h3, l3;
    bsplit(v.x, h0, l0); bsplit(v.y, h1, l1); bsplit(v.z, h2, l2); bsplit(v.w, h3, l3);
    __nv_bfloat16* d = &g_GW[l][n][k];
    *(__nv_bfloat162*)(d)        = __nv_bfloat162(h0, h1);
    *(__nv_bfloat162*)(d + 2)    = __nv_bfloat162(h2, h3);
    *(__nv_bfloat162*)(d + 1024) = __nv_bfloat162(l0, l1);
    *(__nv_bfloat162*)(d + 1026) = __nv_bfloat162(l2, l3);
    *(__nv_bfloat162*)(d + 2048) = __nv_bfloat162(h0, h1);
    *(__nv_bfloat162*)(d + 2050) = __nv_bfloat162(h2, h3);
}

// attn_out_W -> g_AOW: [Wh(1024)|Wl(1024)|Wh(1024)]
__global__ void __launch_bounds__(256) k_cvtAOW(const float* __restrict__ W) {
    size_t t = (size_t)blockIdx.x * 256 + threadIdx.x;   // 512*1024/4
    if (t >= (size_t)EE * 1024 / 4) return;
    int row = (int)(t >> 8);
    int k = (int)(t & 255) * 4;
    float4 v = *(const float4*)(W + (size_t)row * 1024 + k);
    __nv_bfloat16 h0, l0, h1, l1, h2, l2, h3, l3;
    bsplit(v.x, h0, l0); bsplit(v.y, h1, l1); bsplit(v.z, h2, l2); bsplit(v.w, h3, l3);
    __nv_bfloat16* d = &g_AOW[row][k];
    *(__nv_bfloat162*)(d)        = __nv_bfloat162(h0, h1);
    *(__nv_bfloat162*)(d + 2)    = __nv_bfloat162(h2, h3);
    *(__nv_bfloat162*)(d + 1024) = __nv_bfloat162(l0, l1);
    *(__nv_bfloat162*)(d + 1026) = __nv_bfloat162(l2, l3);
    *(__nv_bfloat162*)(d + 2048) = __nv_bfloat162(h0, h1);
    *(__nv_bfloat162*)(d + 2050) = __nv_bfloat162(h2, h3);
}

// ---------------- vocab GEMM via warp-level mma.sync (bf16 -> fp32) ----------------
// C[2048, 32000] = A'[2048,1536] @ W'[32000,1536]^T + gen_b
#define VBK 32

__global__ void __launch_bounds__(256) k_vocab(const float* __restrict__ gen_b,
                                               float* __restrict__ out)
{
    __shared__ __nv_bfloat16 sA[2][128 * LDA];
    __shared__ __nv_bfloat16 sB[2][128 * LDA];

    int tid = threadIdx.x;
    int wid = tid >> 5, lane = tid & 31;
    int n0 = blockIdx.x * 128;
    int m0 = blockIdx.y * 128;
    int wm = (wid & 3) * 32;
    int wn = (wid >> 2) * 64;

    float acc[2][8][4];
    #pragma unroll
    for (int a = 0; a < 2; a++)
        #pragma unroll
        for (int b = 0; b < 8; b++)
            #pragma unroll
            for (int q = 0; q < 4; q++) acc[a][b][q] = 0.f;

    int lrow = tid >> 2;
    int lseg = (tid & 3) * 8;
    const __nv_bfloat16* Ag0 = g_Ap + (size_t)(m0 + lrow)      * KP + lseg;
    const __nv_bfloat16* Ag1 = g_Ap + (size_t)(m0 + lrow + 64) * KP + lseg;
    const __nv_bfloat16* Bg0 = g_Wp + (size_t)(n0 + lrow)      * KP + lseg;
    const __nv_bfloat16* Bg1 = g_Wp + (size_t)(n0 + lrow + 64) * KP + lseg;
    int sr0 = lrow * LDA + lseg;
    int sr1 = (lrow + 64) * LDA + lseg;

    float4 ra0 = *(const float4*)Ag0;
    float4 ra1 = *(const float4*)Ag1;
    float4 rb0 = *(const float4*)Bg0;
    float4 rb1 = *(const float4*)Bg1;

    const int NCH = KP / VBK;   // 48
    for (int c = 0; c < NCH; c++) {
        int cur = c & 1;
        *(float4*)&sA[cur][sr0] = ra0;
        *(float4*)&sA[cur][sr1] = ra1;
        *(float4*)&sB[cur][sr0] = rb0;
        *(float4*)&sB[cur][sr1] = rb1;
        if (c + 1 < NCH) {
            ra0 = *(const float4*)(Ag0 + (c + 1) * VBK);
            ra1 = *(const float4*)(Ag1 + (c + 1) * VBK);
            rb0 = *(const float4*)(Bg0 + (c + 1) * VBK);
            rb1 = *(const float4*)(Bg1 + (c + 1) * VBK);
        }
        __syncthreads();

        #pragma unroll
        for (int ks = 0; ks < 2; ks++) {
            int kc = ks * 16;
            uint32_t afr[2][4];
            #pragma unroll
            for (int am = 0; am < 2; am++) {
                int row = wm + am * 16 + (lane & 15);
                int col = kc + (lane >> 4) * 8;
                uint32_t addr = smem_u32(&sA[cur][row * LDA + col]);
                asm volatile("ldmatrix.sync.aligned.m8n8.x4.shared.b16 {%0,%1,%2,%3}, [%4];"
                    : "=r"(afr[am][0]), "=r"(afr[am][1]), "=r"(afr[am][2]), "=r"(afr[am][3])
                    : "r"(addr));
            }
            uint32_t bfr[4][4];
            #pragma unroll
            for (int bn = 0; bn < 4; bn++) {
                int sub = lane >> 3;
                int row = wn + bn * 16 + (sub >> 1) * 8 + (lane & 7);
                int col = kc + (sub & 1) * 8;
                uint32_t addr = smem_u32(&sB[cur][row * LDA + col]);
                asm volatile("ldmatrix.sync.aligned.m8n8.x4.shared.b16 {%0,%1,%2,%3}, [%4];"
                    : "=r"(bfr[bn][0]), "=r"(bfr[bn][1]), "=r"(bfr[bn][2]), "=r"(bfr[bn][3])
                    : "r"(addr));
            }
            #pragma unroll
            for (int am = 0; am < 2; am++) {
                #pragma unroll
                for (int bn = 0; bn < 8; bn++) {
                    uint32_t b0 = bfr[bn >> 1][(bn & 1) * 2];
                    uint32_t b1 = bfr[bn >> 1][(bn & 1) * 2 + 1];
                    asm volatile(
                        "mma.sync.aligned.m16n8k16.row.col.f32.bf16.bf16.f32 "
                        "{%0,%1,%2,%3}, {%4,%5,%6,%7}, {%8,%9}, {%0,%1,%2,%3};"
                        : "+f"(acc[am][bn][0]), "+f"(acc[am][bn][1]),
                          "+f"(acc[am][bn][2]), "+f"(acc[am][bn][3])
                        : "r"(afr[am][0]), "r"(afr[am][1]), "r"(afr[am][2]), "r"(afr[am][3]),
                          "r"(b0), "r"(b1));
                }
            }
        }
    }

    int group = lane >> 2, tq = (lane & 3) * 2;
    #pragma unroll
    for (int am = 0; am < 2; am++) {
        #pragma unroll
        for (int bn = 0; bn < 8; bn++) {
            int r0 = m0 + wm + am * 16 + group;
            int cx = n0 + wn + bn * 8 + tq;
            float b0 = gen_b[cx], b1 = gen_b[cx + 1];
            float2 v0 = { acc[am][bn][0] + b0, acc[am][bn][1] + b1 };
            float2 v1 = { acc[am][bn][2] + b0, acc[am][bn][3] + b1 };
            *(float2*)&out[(size_t)r0 * VV + cx]       = v0;
            *(float2*)&out[(size_t)(r0 + 8) * VV + cx] = v1;
        }
    }
}

// ---------------- final state copy ----------------
__global__ void k_fin(float* __restrict__ out) {
    int i = blockIdx.x * 256 + threadIdx.x;
    int n = NL * BB * HH;
    if (i < n)           out[i] = ((const float*)g_h)[i];
    else if (i < 2 * n)  out[i] = ((const float*)g_c)[i - n];
}

// ---------------- launch ----------------
extern "C" void kernel_launch(void* const* d_in, const int* in_sizes, int n_in,
                              void* d_out, int out_size) {
    int o = (n_in >= 15) ? 1 : 0;   // optional scalar 'length'
    const int*   cur        = (const int*)  d_in[0];
    const float* h0         = (const float*)d_in[1];
    const float* c0         = (const float*)d_in[2];
    const float* enc        = (const float*)d_in[3];
    const int*   gtr        = (const int*)  d_in[4];
    const float* emb        = (const float*)d_in[5 + o];
    const float* attn_W     = (const float*)d_in[6 + o];
    const float* attn_out_W = (const float*)d_in[7 + o];
    const float* Wi         = (const float*)d_in[8 + o];
    const float* Wh         = (const float*)d_in[9 + o];
    const float* bi         = (const float*)d_in[10 + o];
    const float* bh         = (const float*)d_in[11 + o];
    const float* gen_W      = (const float*)d_in[12 + o];
    const float* gen_b      = (const float*)d_in[13 + o];
    float* out = (float*)d_out;

    k_init<<<(NL * BB * HH + 255) / 256, 256>>>(h0, c0);
    k_cvtW<<<(VV * 512 / 4 + 255) / 256, 256>>>(gen_W);
    k_cvtGW<<<((NL * 4 * HH * 1024 / 4) + 255) / 256, 256>>>(Wi, Wh);
    k_cvtAOW<<<((EE * 1024 / 4) + 255) / 256, 256>>>(attn_out_W);

    for (int t = 0; t < TT; t++) {
        const int* tok = (t == 0) ? cur : (gtr + (size_t)(t - 1) * BB);
        k_attn<<<BB, 256>>>(tok, emb, attn_W, enc);

        k_rgemm<<<dim3(EE / 128, 1, KS), 256>>>(0);     // rnn_in partials
        k_comb<<<(BB * EE) / 256, 256>>>();

        k_rgemm<<<dim3(4 * HH / 128, 1, KS), 256>>>(1); // gates l0
        k_cell<<<(BB * HH) / 256, 256>>>(bi, bh, 0, t);

        k_rgemm<<<dim3(4 * HH / 128, 1, KS), 256>>>(2); // gates l1
        k_cell<<<(BB * HH) / 256, 256>>>(bi, bh, 1, t);
    }

    // vocab GEMM (A' rows already written by k_cell l=1)
    k_vocab<<<dim3(VV / 128, (TT * BB) / 128), 256>>>(gen_b, out);

    size_t sn = (size_t)TT * BB * VV;
    if ((size_t)out_size >= sn + (size_t)2 * NL * BB * HH)
        k_fin<<<(2 * NL * BB * HH + 255) / 256, 256>>>(out + sn);
}